// round 4
// baseline (speedup 1.0000x reference)
#include <cuda_runtime.h>
#include <cuda_fp16.h>
#include <cstdint>

#define EMBED 8192
#define U0 1024
#define KH 1040
#define U1 256
#define NHEAD 6
#define BATCH 8192

__device__ __align__(16) __half g_xh[(size_t)BATCH * EMBED];
__device__ __align__(16) __half g_xl[(size_t)BATCH * EMBED];
__device__ __align__(16) __half g_Wt[(size_t)U0 * EMBED];
__device__ __align__(16) float g_h[(size_t)BATCH * KH];
__device__ int g_idx[BATCH];
__device__ int g_cnt[NHEAD];
__device__ int g_off[NHEAD];

__device__ __forceinline__ uint32_t smem_u32(const void* p) {
    uint32_t a;
    asm("{ .reg .u64 t; cvta.to.shared.u64 t, %1; cvt.u32.u64 %0, t; }" : "=r"(a) : "l"(p));
    return a;
}

#define CP_ASYNC16(dst, src) \
    asm volatile("cp.async.cg.shared.global [%0], [%1], 16;" ::"r"(dst), "l"(src))
#define CP_COMMIT() asm volatile("cp.async.commit_group;" ::: "memory")
#define CP_WAIT2()  asm volatile("cp.async.wait_group 2;" ::: "memory")

#define LDMX4(r0, r1, r2, r3, a) \
    asm volatile("ldmatrix.sync.aligned.m8n8.x4.shared.b16 {%0,%1,%2,%3}, [%4];" \
        : "=r"(r0), "=r"(r1), "=r"(r2), "=r"(r3) : "r"(a))

#define MMA16816(c, a, b0, b1)                                                   \
    asm volatile("mma.sync.aligned.m16n8k16.row.col.f32.f16.f16.f32 "            \
        "{%0,%1,%2,%3}, {%4,%5,%6,%7}, {%8,%9}, {%0,%1,%2,%3};"                  \
        : "+f"((c)[0]), "+f"((c)[1]), "+f"((c)[2]), "+f"((c)[3])                 \
        : "r"((a)[0]), "r"((a)[1]), "r"((a)[2]), "r"((a)[3]), "r"(b0), "r"(b1))

// ============ K1: x -> fp16 hi/lo split ============
__global__ void convert_x_kernel(const float* __restrict__ x) {
    size_t i = (size_t)blockIdx.x * 256 + threadIdx.x;  // per float4
    const float4 v = reinterpret_cast<const float4*>(x)[i];
    __half hx = __float2half_rn(v.x), hy = __float2half_rn(v.y);
    __half hz = __float2half_rn(v.z), hw = __float2half_rn(v.w);
    __half lx = __float2half_rn(v.x - __half2float(hx));
    __half ly = __float2half_rn(v.y - __half2float(hy));
    __half lz = __float2half_rn(v.z - __half2float(hz));
    __half lw = __float2half_rn(v.w - __half2float(hw));
    uint2 ph, pl;
    ph.x = (uint32_t)__half_as_ushort(hx) | ((uint32_t)__half_as_ushort(hy) << 16);
    ph.y = (uint32_t)__half_as_ushort(hz) | ((uint32_t)__half_as_ushort(hw) << 16);
    pl.x = (uint32_t)__half_as_ushort(lx) | ((uint32_t)__half_as_ushort(ly) << 16);
    pl.y = (uint32_t)__half_as_ushort(lz) | ((uint32_t)__half_as_ushort(lw) << 16);
    reinterpret_cast<uint2*>(g_xh)[i] = ph;
    reinterpret_cast<uint2*>(g_xl)[i] = pl;
}

// ============ K2: transpose fc_W [K][N] fp32 -> g_Wt [N][K] fp16 ============
__global__ void convert_w_kernel(const float* __restrict__ W) {
    __shared__ float tile[32][33];
    const int bx = blockIdx.x, by = blockIdx.y;
    const int tx = threadIdx.x, ty = threadIdx.y;
#pragma unroll
    for (int r = 0; r < 4; r++)
        tile[ty + r * 8][tx] = W[(size_t)(by * 32 + ty + r * 8) * U0 + bx * 32 + tx];
    __syncthreads();
#pragma unroll
    for (int r = 0; r < 4; r++) {
        int n = bx * 32 + ty + r * 8, k = by * 32 + tx;
        g_Wt[(size_t)n * EMBED + k] = __float2half_rn(tile[tx][ty + r * 8]);
    }
}

// ============ K3: ego columns + zero pad of g_h cols [1024,1040) ============
__global__ void ego_kernel(const float* __restrict__ ego) {
    int i = blockIdx.x * 256 + threadIdx.x;
    if (i >= BATCH * 16) return;
    int b = i >> 4, j = i & 15;
    g_h[(size_t)b * KH + U0 + j] = (j < 3) ? ego[b * 3 + j] : 0.f;
}

// ============ K4: bin rows by command (1 block) ============
__global__ void prep_kernel(const int* __restrict__ cmd) {
    __shared__ int scnt[NHEAD], scur[NHEAD];
    const int tid = threadIdx.x;
    if (tid < NHEAD) scnt[tid] = 0;
    __syncthreads();
    for (int b = tid; b < BATCH; b += 256) {
        int c = cmd[b];
        unsigned m = __match_any_sync(0xFFFFFFFFu, c);
        if ((tid & 31) == __ffs(m) - 1) atomicAdd(&scnt[c], __popc(m));
    }
    __syncthreads();
    if (tid == 0) {
        int run = 0;
        for (int g = 0; g < NHEAD; g++) { g_off[g] = run; g_cnt[g] = scnt[g]; scur[g] = run; run += scnt[g]; }
    }
    __syncthreads();
    for (int b = tid; b < BATCH; b += 256) {
        int c = cmd[b];
        unsigned m = __match_any_sync(0xFFFFFFFFu, c);
        int leader = __ffs(m) - 1, base = 0;
        if ((tid & 31) == leader) base = atomicAdd(&scur[c], __popc(m));
        base = __shfl_sync(m, base, leader);
        g_idx[base + __popc(m & ((1u << (tid & 31)) - 1u))] = b;
    }
}

// ============ K5: GEMM1 h = relu(x @ fc_W + b), fp16 2-term mma.sync ============
// BM=128 BN=128 BK=32, 256 threads (8 warps as 2m x 4n), 4-stage cp.async.
// Stage layout (24 KB): Ah [128][32] h @+0, Al @+8192, Wh [128][32] h @+16384.
#define STG_BYTES 24576
#define NSTAGE 4
#define NITER 256

__global__ void __launch_bounds__(256, 1) gemm1_kernel(const float* __restrict__ fcb) {
    extern __shared__ char smem[];
    const uint32_t sb = smem_u32(smem);
    const int tid = threadIdx.x;
    const int wid = tid >> 5, lane = tid & 31;
    const int wm = wid & 1, wn = wid >> 1;
    const int m0 = blockIdx.y * 128, n0 = blockIdx.x * 128;

    const __half* xh = g_xh + (size_t)m0 * EMBED;
    const __half* xl = g_xl + (size_t)m0 * EMBED;
    const __half* wt = g_Wt + (size_t)n0 * EMBED;

    // chunk decomposition for loads: q in [0,512): r=q>>2 (row), c=q&3 (16B chunk)
    const int lr = tid >> 2, lc = tid & 3;
    const uint32_t lsw0 = (uint32_t)(lr * 64 + ((lc ^ ((lr >> 1) & 3)) << 4));
    const int lr1 = (tid + 256) >> 2, lc1 = (tid + 256) & 3;
    const uint32_t lsw1 = (uint32_t)(lr1 * 64 + ((lc1 ^ ((lr1 >> 1) & 3)) << 4));

#define LOAD_STAGE(stg, k0) do {                                                  \
    uint32_t bsa = sb + (stg) * STG_BYTES;                                        \
    const __half* sa0 = xh + (size_t)lr * EMBED + (k0) + lc * 8;                  \
    const __half* sa1 = xh + (size_t)lr1 * EMBED + (k0) + lc1 * 8;                \
    CP_ASYNC16(bsa + lsw0, sa0);                                                  \
    CP_ASYNC16(bsa + lsw1, sa1);                                                  \
    const __half* sb0_ = xl + (size_t)lr * EMBED + (k0) + lc * 8;                 \
    const __half* sb1_ = xl + (size_t)lr1 * EMBED + (k0) + lc1 * 8;               \
    CP_ASYNC16(bsa + 8192 + lsw0, sb0_);                                          \
    CP_ASYNC16(bsa + 8192 + lsw1, sb1_);                                          \
    const __half* sw0 = wt + (size_t)lr * EMBED + (k0) + lc * 8;                  \
    const __half* sw1 = wt + (size_t)lr1 * EMBED + (k0) + lc1 * 8;                \
    CP_ASYNC16(bsa + 16384 + lsw0, sw0);                                          \
    CP_ASYNC16(bsa + 16384 + lsw1, sw1);                                          \
} while (0)

    LOAD_STAGE(0, 0);  CP_COMMIT();
    LOAD_STAGE(1, 32); CP_COMMIT();
    LOAD_STAGE(2, 64); CP_COMMIT();

    float acc[4][4][4];
#pragma unroll
    for (int f = 0; f < 4; f++)
#pragma unroll
        for (int n = 0; n < 4; n++)
#pragma unroll
            for (int j = 0; j < 4; j++) acc[f][n][j] = 0.f;

    // ldmatrix per-thread row/chunk pieces
    const int trow = (lane & 7) + ((lane >> 3) & 1) * 8;  // row within 16-block
    const int tkc = lane >> 4;                            // k-chunk 0/1 within k16

    for (int it = 0; it < NITER; it++) {
        CP_WAIT2();
        __syncthreads();
        if (it + 3 < NITER) LOAD_STAGE((it + 3) & 3, (it + 3) * 32);
        CP_COMMIT();

        const uint32_t sA = sb + (it & 3) * STG_BYTES;
#pragma unroll
        for (int ks = 0; ks < 2; ks++) {
            uint32_t ah[4][4], al[4][4];
            uint32_t bf[4][2];
            const int kc = ks * 2 + tkc;
#pragma unroll
            for (int f = 0; f < 4; f++) {
                int row = wm * 64 + f * 16 + trow;
                uint32_t ad = sA + row * 64 + ((kc ^ ((row >> 1) & 3)) << 4);
                LDMX4(ah[f][0], ah[f][1], ah[f][2], ah[f][3], ad);
                LDMX4(al[f][0], al[f][1], al[f][2], al[f][3], ad + 8192);
            }
#pragma unroll
            for (int p = 0; p < 2; p++) {
                int row = wn * 32 + p * 16 + trow;
                uint32_t bd = sA + 16384 + row * 64 + ((kc ^ ((row >> 1) & 3)) << 4);
                uint32_t r0, r1, r2, r3;
                LDMX4(r0, r1, r2, r3, bd);
                bf[2 * p][0] = r0; bf[2 * p][1] = r2;
                bf[2 * p + 1][0] = r1; bf[2 * p + 1][1] = r3;
            }
#pragma unroll
            for (int f = 0; f < 4; f++)
#pragma unroll
                for (int n = 0; n < 4; n++) {
                    MMA16816(acc[f][n], ah[f], bf[n][0], bf[n][1]);
                    MMA16816(acc[f][n], al[f], bf[n][0], bf[n][1]);
                }
        }
    }

    // epilogue: bias + relu, direct store
    const int qr = lane >> 2, qc = (lane & 3) << 1;
#pragma unroll
    for (int f = 0; f < 4; f++) {
#pragma unroll
        for (int n = 0; n < 4; n++) {
            int col = n0 + wn * 32 + n * 8 + qc;
            float b0 = fcb[col], b1 = fcb[col + 1];
            int row = m0 + wm * 64 + f * 16 + qr;
            float2 v0, v1;
            v0.x = fmaxf(acc[f][n][0] + b0, 0.f);
            v0.y = fmaxf(acc[f][n][1] + b1, 0.f);
            v1.x = fmaxf(acc[f][n][2] + b0, 0.f);
            v1.y = fmaxf(acc[f][n][3] + b1, 0.f);
            *reinterpret_cast<float2*>(&g_h[(size_t)row * KH + col]) = v0;
            *reinterpret_cast<float2*>(&g_h[(size_t)(row + 8) * KH + col]) = v1;
        }
    }
}

// ============ K6: binned per-head MLP (1027->256 relu ->4) + epilogue ============
__global__ void __launch_bounds__(256) phase2_kernel(const float* __restrict__ W1,
                                                     const float* __restrict__ b1,
                                                     const float* __restrict__ W2,
                                                     const float* __restrict__ b2,
                                                     float* __restrict__ out) {
    __shared__ float buf[32 * 260];
    __shared__ int ridx[32];
    const int hd = blockIdx.y;
    const int cnt = g_cnt[hd], base = g_off[hd];
    const int r0 = blockIdx.x * 32;
    if (r0 >= cnt) return;
    const int tid = threadIdx.x;
    if (tid < 32) {
        int rr = r0 + tid;
        ridx[tid] = g_idx[base + (rr < cnt ? rr : 0)];
    }
    __syncthreads();
    const int tx = tid & 63, ty = tid >> 6;
    float acc[8][4];
#pragma unroll
    for (int i = 0; i < 8; i++)
#pragma unroll
        for (int j = 0; j < 4; j++) acc[i][j] = 0.f;
    const float* W1h = W1 + (size_t)hd * 1027 * 256;

    for (int kc = 0; kc < 13; kc++) {
        __syncthreads();
#pragma unroll
        for (int j = 0; j < 10; j++) {
            int q = tid + 256 * j, r = q / 80, cc = q % 80;
            buf[r * 80 + cc] = g_h[(size_t)ridx[r] * KH + kc * 80 + cc];
        }
        __syncthreads();
        const int kb = kc * 80;
#pragma unroll 4
        for (int k = 0; k < 80; k++) {
            int kk = min(kb + k, 1026);
            const float4 w = *(reinterpret_cast<const float4*>(W1h + (size_t)kk * 256) + tx);
#pragma unroll
            for (int i = 0; i < 8; i++) {
                float hv = buf[(ty * 8 + i) * 80 + k];
                acc[i][0] += hv * w.x; acc[i][1] += hv * w.y;
                acc[i][2] += hv * w.z; acc[i][3] += hv * w.w;
            }
        }
    }
    __syncthreads();
#pragma unroll
    for (int i = 0; i < 8; i++) {
        int r = ty * 8 + i;
#pragma unroll
        for (int j = 0; j < 4; j++) {
            float v = acc[i][j] + b1[hd * 256 + tx * 4 + j];
            buf[r * 260 + tx * 4 + j] = fmaxf(v, 0.f);
        }
    }
    __syncthreads();
    if (tid < 128) {
        int row = tid >> 2, o = tid & 3;
        const float* W2h = W2 + hd * 256 * 4;
        float a = b2[hd * 4 + o];
#pragma unroll 8
        for (int k = 0; k < 256; k++) a += buf[row * 260 + k] * W2h[k * 4 + o];
        int rr = r0 + row;
        if (rr < cnt) {
            int bi = ridx[row];
            float v;
            if (o < 2) {
                v = 5.f * tanhf(a * 0.2f);
            } else {
                float t = a + 4.9932394f;
                v = ((t > 20.f) ? t : log1pf(expf(t))) + 1e-4f;
            }
            out[bi * 4 + o] = v;
        }
    }
}

extern "C" void kernel_launch(void* const* d_in, const int* in_sizes, int n_in,
                              void* d_out, int out_size) {
    const float* x   = (const float*)d_in[0];
    const int* cmd   = (const int*)d_in[1];
    const float* ego = (const float*)d_in[2];
    const float* fcW = (const float*)d_in[3];
    const float* fcb = (const float*)d_in[4];
    const float* W1  = (const float*)d_in[5];
    const float* b1  = (const float*)d_in[6];
    const float* W2  = (const float*)d_in[7];
    const float* b2  = (const float*)d_in[8];
    float* out = (float*)d_out;

    static int smem_set = 0;
    if (!smem_set) {
        cudaFuncSetAttribute(gemm1_kernel, cudaFuncAttributeMaxDynamicSharedMemorySize,
                             NSTAGE * STG_BYTES);
        smem_set = 1;
    }

    convert_x_kernel<<<(BATCH * EMBED / 4) / 256, 256>>>(x);
    convert_w_kernel<<<dim3(32, 256), dim3(32, 8)>>>(fcW);
    ego_kernel<<<(BATCH * 16) / 256, 256>>>(ego);
    prep_kernel<<<1, 256>>>(cmd);
    gemm1_kernel<<<dim3(8, 64), 256, NSTAGE * STG_BYTES>>>(fcb);
    phase2_kernel<<<dim3(BATCH / 32, NHEAD), 256>>>(W1, b1, W2, b2, out);
}

// round 5
// speedup vs baseline: 1.4174x; 1.4174x over previous
#include <cuda_runtime.h>
#include <cuda_fp16.h>
#include <cstdint>

#define EMBED 8192
#define U0 1024
#define KH 1040
#define U1 256
#define NHEAD 6
#define BATCH 8192

__device__ __align__(16) __half g_xh[(size_t)BATCH * EMBED];
__device__ __align__(16) __half g_Wt[(size_t)U0 * EMBED];
__device__ __align__(16) float g_h[(size_t)BATCH * KH];
__device__ int g_idx[BATCH];
__device__ int g_cnt[NHEAD];
__device__ int g_off[NHEAD];

__device__ __forceinline__ uint32_t smem_u32(const void* p) {
    uint32_t a;
    asm("{ .reg .u64 t; cvta.to.shared.u64 t, %1; cvt.u32.u64 %0, t; }" : "=r"(a) : "l"(p));
    return a;
}

#define CP_ASYNC16(dst, src) \
    asm volatile("cp.async.cg.shared.global [%0], [%1], 16;" ::"r"(dst), "l"(src))
#define CP_COMMIT() asm volatile("cp.async.commit_group;" ::: "memory")
#define CP_WAIT2()  asm volatile("cp.async.wait_group 2;" ::: "memory")

#define LDMX4(r0, r1, r2, r3, a) \
    asm volatile("ldmatrix.sync.aligned.m8n8.x4.shared.b16 {%0,%1,%2,%3}, [%4];" \
        : "=r"(r0), "=r"(r1), "=r"(r2), "=r"(r3) : "r"(a))

#define MMA16816(c, a, b0, b1)                                                   \
    asm volatile("mma.sync.aligned.m16n8k16.row.col.f32.f16.f16.f32 "            \
        "{%0,%1,%2,%3}, {%4,%5,%6,%7}, {%8,%9}, {%0,%1,%2,%3};"                  \
        : "+f"((c)[0]), "+f"((c)[1]), "+f"((c)[2]), "+f"((c)[3])                 \
        : "r"((a)[0]), "r"((a)[1]), "r"((a)[2]), "r"((a)[3]), "r"(b0), "r"(b1))

// ============ K1: x -> fp16 (single term) ============
__global__ void convert_x_kernel(const float* __restrict__ x) {
    size_t i = (size_t)blockIdx.x * 256 + threadIdx.x;  // per float4
    const float4 v = reinterpret_cast<const float4*>(x)[i];
    uint2 ph;
    ph.x = (uint32_t)__half_as_ushort(__float2half_rn(v.x)) |
           ((uint32_t)__half_as_ushort(__float2half_rn(v.y)) << 16);
    ph.y = (uint32_t)__half_as_ushort(__float2half_rn(v.z)) |
           ((uint32_t)__half_as_ushort(__float2half_rn(v.w)) << 16);
    reinterpret_cast<uint2*>(g_xh)[i] = ph;
}

// ============ K2: transpose fc_W [K][N] fp32 -> g_Wt [N][K] fp16 ============
__global__ void convert_w_kernel(const float* __restrict__ W) {
    __shared__ float tile[32][33];
    const int bx = blockIdx.x, by = blockIdx.y;
    const int tx = threadIdx.x, ty = threadIdx.y;
#pragma unroll
    for (int r = 0; r < 4; r++)
        tile[ty + r * 8][tx] = W[(size_t)(by * 32 + ty + r * 8) * U0 + bx * 32 + tx];
    __syncthreads();
#pragma unroll
    for (int r = 0; r < 4; r++) {
        int n = bx * 32 + ty + r * 8, k = by * 32 + tx;
        g_Wt[(size_t)n * EMBED + k] = __float2half_rn(tile[tx][ty + r * 8]);
    }
}

// ============ K3: ego columns + zero pad of g_h cols [1024,1040) ============
__global__ void ego_kernel(const float* __restrict__ ego) {
    int i = blockIdx.x * 256 + threadIdx.x;
    if (i >= BATCH * 16) return;
    int b = i >> 4, j = i & 15;
    g_h[(size_t)b * KH + U0 + j] = (j < 3) ? ego[b * 3 + j] : 0.f;
}

// ============ K4: bin rows by command (1 block) ============
__global__ void prep_kernel(const int* __restrict__ cmd) {
    __shared__ int scnt[NHEAD], scur[NHEAD];
    const int tid = threadIdx.x;
    if (tid < NHEAD) scnt[tid] = 0;
    __syncthreads();
    for (int b = tid; b < BATCH; b += 256) {
        int c = cmd[b];
        unsigned m = __match_any_sync(0xFFFFFFFFu, c);
        if ((tid & 31) == __ffs(m) - 1) atomicAdd(&scnt[c], __popc(m));
    }
    __syncthreads();
    if (tid == 0) {
        int run = 0;
        for (int g = 0; g < NHEAD; g++) { g_off[g] = run; g_cnt[g] = scnt[g]; scur[g] = run; run += scnt[g]; }
    }
    __syncthreads();
    for (int b = tid; b < BATCH; b += 256) {
        int c = cmd[b];
        unsigned m = __match_any_sync(0xFFFFFFFFu, c);
        int leader = __ffs(m) - 1, base = 0;
        if ((tid & 31) == leader) base = atomicAdd(&scur[c], __popc(m));
        base = __shfl_sync(m, base, leader);
        g_idx[base + __popc(m & ((1u << (tid & 31)) - 1u))] = b;
    }
}

// ============ K5: GEMM1 h = relu(x @ fc_W + b), single-term fp16 mma.sync ============
// BM=128 BN=128 BK=32, 256 threads (8 warps as 2m x 4n), 4-stage cp.async.
// Stage layout (16 KB): A [128][32] h @+0, W [128][32] h @+8192.
#define STG_BYTES 16384
#define NSTAGE 4
#define NITER 256

__global__ void __launch_bounds__(256) gemm1_kernel(const float* __restrict__ fcb) {
    extern __shared__ char smem[];
    const uint32_t sb = smem_u32(smem);
    const int tid = threadIdx.x;
    const int wid = tid >> 5, lane = tid & 31;
    const int wm = wid & 1, wn = wid >> 1;
    const int m0 = blockIdx.y * 128, n0 = blockIdx.x * 128;

    const __half* xh = g_xh + (size_t)m0 * EMBED;
    const __half* wt = g_Wt + (size_t)n0 * EMBED;

    const int lr = tid >> 2, lc = tid & 3;
    const uint32_t lsw0 = (uint32_t)(lr * 64 + ((lc ^ ((lr >> 1) & 3)) << 4));
    const int lr1 = (tid + 256) >> 2, lc1 = (tid + 256) & 3;
    const uint32_t lsw1 = (uint32_t)(lr1 * 64 + ((lc1 ^ ((lr1 >> 1) & 3)) << 4));

#define LOAD_STAGE(stg, k0) do {                                                  \
    uint32_t bsa = sb + (stg) * STG_BYTES;                                        \
    CP_ASYNC16(bsa + lsw0, xh + (size_t)lr * EMBED + (k0) + lc * 8);              \
    CP_ASYNC16(bsa + lsw1, xh + (size_t)lr1 * EMBED + (k0) + lc1 * 8);            \
    CP_ASYNC16(bsa + 8192 + lsw0, wt + (size_t)lr * EMBED + (k0) + lc * 8);       \
    CP_ASYNC16(bsa + 8192 + lsw1, wt + (size_t)lr1 * EMBED + (k0) + lc1 * 8);     \
} while (0)

    LOAD_STAGE(0, 0);  CP_COMMIT();
    LOAD_STAGE(1, 32); CP_COMMIT();
    LOAD_STAGE(2, 64); CP_COMMIT();

    float acc[4][4][4];
#pragma unroll
    for (int f = 0; f < 4; f++)
#pragma unroll
        for (int n = 0; n < 4; n++)
#pragma unroll
            for (int j = 0; j < 4; j++) acc[f][n][j] = 0.f;

    const int trow = (lane & 7) + ((lane >> 3) & 1) * 8;
    const int tkc = lane >> 4;

    for (int it = 0; it < NITER; it++) {
        CP_WAIT2();
        __syncthreads();
        if (it + 3 < NITER) LOAD_STAGE((it + 3) & 3, (it + 3) * 32);
        CP_COMMIT();

        const uint32_t sA = sb + (it & 3) * STG_BYTES;
#pragma unroll
        for (int ks = 0; ks < 2; ks++) {
            uint32_t ah[4][4];
            uint32_t bf[4][2];
            const int kc = ks * 2 + tkc;
#pragma unroll
            for (int f = 0; f < 4; f++) {
                int row = wm * 64 + f * 16 + trow;
                uint32_t ad = sA + row * 64 + ((kc ^ ((row >> 1) & 3)) << 4);
                LDMX4(ah[f][0], ah[f][1], ah[f][2], ah[f][3], ad);
            }
#pragma unroll
            for (int p = 0; p < 2; p++) {
                int row = wn * 32 + p * 16 + trow;
                uint32_t bd = sA + 8192 + row * 64 + ((kc ^ ((row >> 1) & 3)) << 4);
                uint32_t r0, r1, r2, r3;
                LDMX4(r0, r1, r2, r3, bd);
                bf[2 * p][0] = r0; bf[2 * p][1] = r2;
                bf[2 * p + 1][0] = r1; bf[2 * p + 1][1] = r3;
            }
#pragma unroll
            for (int f = 0; f < 4; f++)
#pragma unroll
                for (int n = 0; n < 4; n++)
                    MMA16816(acc[f][n], ah[f], bf[n][0], bf[n][1]);
        }
    }

    const int qr = lane >> 2, qc = (lane & 3) << 1;
#pragma unroll
    for (int f = 0; f < 4; f++) {
#pragma unroll
        for (int n = 0; n < 4; n++) {
            int col = n0 + wn * 32 + n * 8 + qc;
            float b0 = fcb[col], b1 = fcb[col + 1];
            int row = m0 + wm * 64 + f * 16 + qr;
            float2 v0, v1;
            v0.x = fmaxf(acc[f][n][0] + b0, 0.f);
            v0.y = fmaxf(acc[f][n][1] + b1, 0.f);
            v1.x = fmaxf(acc[f][n][2] + b0, 0.f);
            v1.y = fmaxf(acc[f][n][3] + b1, 0.f);
            *reinterpret_cast<float2*>(&g_h[(size_t)row * KH + col]) = v0;
            *reinterpret_cast<float2*>(&g_h[(size_t)(row + 8) * KH + col]) = v1;
        }
    }
}

// ============ K6: binned per-head MLP (1027->256 relu ->4), 64 rows/block ============
#define P2R 64
#define P2SMEM (P2R * 260 * 4)

__global__ void __launch_bounds__(256) phase2_kernel(const float* __restrict__ W1,
                                                     const float* __restrict__ b1,
                                                     const float* __restrict__ W2,
                                                     const float* __restrict__ b2,
                                                     float* __restrict__ out) {
    extern __shared__ char smem[];
    float* buf = reinterpret_cast<float*>(smem);  // max(64*80, 64*260) floats
    __shared__ int ridx[P2R];
    const int hd = blockIdx.y;
    const int cnt = g_cnt[hd], base = g_off[hd];
    const int r0 = blockIdx.x * P2R;
    if (r0 >= cnt) return;
    const int tid = threadIdx.x;
    if (tid < P2R) {
        int rr = r0 + tid;
        ridx[tid] = g_idx[base + (rr < cnt ? rr : 0)];
    }
    __syncthreads();
    const int tx = tid & 63, ty = tid >> 6;  // 64 col-quads x 4 row-groups
    float acc[16][4];
#pragma unroll
    for (int i = 0; i < 16; i++)
#pragma unroll
        for (int j = 0; j < 4; j++) acc[i][j] = 0.f;
    const float* W1h = W1 + (size_t)hd * 1027 * 256;

    for (int kc = 0; kc < 13; kc++) {
        __syncthreads();
#pragma unroll
        for (int j = 0; j < 20; j++) {
            int q = tid + 256 * j, r = q / 80, cc = q % 80;
            buf[r * 80 + cc] = g_h[(size_t)ridx[r] * KH + kc * 80 + cc];
        }
        __syncthreads();
        const int kb = kc * 80;
#pragma unroll 4
        for (int k = 0; k < 80; k++) {
            int kk = min(kb + k, 1026);
            const float4 w = *(reinterpret_cast<const float4*>(W1h + (size_t)kk * 256) + tx);
#pragma unroll
            for (int i = 0; i < 16; i++) {
                float hv = buf[(ty * 16 + i) * 80 + k];
                acc[i][0] += hv * w.x; acc[i][1] += hv * w.y;
                acc[i][2] += hv * w.z; acc[i][3] += hv * w.w;
            }
        }
    }
    __syncthreads();
#pragma unroll
    for (int i = 0; i < 16; i++) {
        int r = ty * 16 + i;
#pragma unroll
        for (int j = 0; j < 4; j++) {
            float v = acc[i][j] + b1[hd * 256 + tx * 4 + j];
            buf[r * 260 + tx * 4 + j] = fmaxf(v, 0.f);
        }
    }
    __syncthreads();
    {
        int row = tid >> 2, o = tid & 3;  // 64 rows x 4 outputs
        const float* W2h = W2 + hd * 256 * 4;
        float a = b2[hd * 4 + o];
#pragma unroll 8
        for (int k = 0; k < 256; k++) a += buf[row * 260 + k] * W2h[k * 4 + o];
        int rr = r0 + row;
        if (rr < cnt) {
            int bi = ridx[row];
            float v;
            if (o < 2) {
                v = 5.f * tanhf(a * 0.2f);
            } else {
                float t = a + 4.9932394f;
                v = ((t > 20.f) ? t : log1pf(expf(t))) + 1e-4f;
            }
            out[bi * 4 + o] = v;
        }
    }
}

extern "C" void kernel_launch(void* const* d_in, const int* in_sizes, int n_in,
                              void* d_out, int out_size) {
    const float* x   = (const float*)d_in[0];
    const int* cmd   = (const int*)d_in[1];
    const float* ego = (const float*)d_in[2];
    const float* fcW = (const float*)d_in[3];
    const float* fcb = (const float*)d_in[4];
    const float* W1  = (const float*)d_in[5];
    const float* b1  = (const float*)d_in[6];
    const float* W2  = (const float*)d_in[7];
    const float* b2  = (const float*)d_in[8];
    float* out = (float*)d_out;

    static int smem_set = 0;
    if (!smem_set) {
        cudaFuncSetAttribute(gemm1_kernel, cudaFuncAttributeMaxDynamicSharedMemorySize,
                             NSTAGE * STG_BYTES);
        cudaFuncSetAttribute(phase2_kernel, cudaFuncAttributeMaxDynamicSharedMemorySize,
                             P2SMEM);
        smem_set = 1;
    }

    convert_x_kernel<<<(BATCH * EMBED / 4) / 256, 256>>>(x);
    convert_w_kernel<<<dim3(32, 256), dim3(32, 8)>>>(fcW);
    ego_kernel<<<(BATCH * 16) / 256, 256>>>(ego);
    prep_kernel<<<1, 256>>>(cmd);
    gemm1_kernel<<<dim3(8, 64), 256, NSTAGE * STG_BYTES>>>(fcb);
    phase2_kernel<<<dim3(BATCH / P2R, NHEAD), 256, P2SMEM>>>(W1, b1, W2, b2, out);
}

// round 7
// speedup vs baseline: 1.5365x; 1.0840x over previous
#include <cuda_runtime.h>
#include <cuda_fp16.h>
#include <cstdint>

#define EMBED 8192
#define U0 1024
#define KH 1040
#define U1 256
#define NHEAD 6
#define BATCH 8192

__device__ __align__(16) __half g_xh[(size_t)BATCH * EMBED];
__device__ __align__(16) __half g_Wt[(size_t)U0 * EMBED];
__device__ __align__(16) float g_h[(size_t)BATCH * KH];
__device__ int g_idx[BATCH];
__device__ int g_cnt[NHEAD];
__device__ int g_off[NHEAD];

__device__ __forceinline__ uint32_t smem_u32(const void* p) {
    uint32_t a;
    asm("{ .reg .u64 t; cvta.to.shared.u64 t, %1; cvt.u32.u64 %0, t; }" : "=r"(a) : "l"(p));
    return a;
}

#define CP_ASYNC16(dst, src) \
    asm volatile("cp.async.cg.shared.global [%0], [%1], 16;" ::"r"(dst), "l"(src))
#define CP_COMMIT() asm volatile("cp.async.commit_group;" ::: "memory")
#define CP_WAIT2()  asm volatile("cp.async.wait_group 2;" ::: "memory")

#define LDMX4(r0, r1, r2, r3, a) \
    asm volatile("ldmatrix.sync.aligned.m8n8.x4.shared.b16 {%0,%1,%2,%3}, [%4];" \
        : "=r"(r0), "=r"(r1), "=r"(r2), "=r"(r3) : "r"(a))

#define MMA16816(c, a, b0, b1)                                                   \
    asm volatile("mma.sync.aligned.m16n8k16.row.col.f32.f16.f16.f32 "            \
        "{%0,%1,%2,%3}, {%4,%5,%6,%7}, {%8,%9}, {%0,%1,%2,%3};"                  \
        : "+f"((c)[0]), "+f"((c)[1]), "+f"((c)[2]), "+f"((c)[3])                 \
        : "r"((a)[0]), "r"((a)[1]), "r"((a)[2]), "r"((a)[3]), "r"(b0), "r"(b1))

// ============ K1: x -> fp16 ============
__global__ void convert_x_kernel(const float* __restrict__ x) {
    size_t i = (size_t)blockIdx.x * 256 + threadIdx.x;
    const float4 v = reinterpret_cast<const float4*>(x)[i];
    uint2 ph;
    ph.x = (uint32_t)__half_as_ushort(__float2half_rn(v.x)) |
           ((uint32_t)__half_as_ushort(__float2half_rn(v.y)) << 16);
    ph.y = (uint32_t)__half_as_ushort(__float2half_rn(v.z)) |
           ((uint32_t)__half_as_ushort(__float2half_rn(v.w)) << 16);
    reinterpret_cast<uint2*>(g_xh)[i] = ph;
}

// ============ K2: transpose fc_W [K][N] fp32 -> g_Wt [N][K] fp16 ============
__global__ void convert_w_kernel(const float* __restrict__ W) {
    __shared__ float tile[32][33];
    const int bx = blockIdx.x, by = blockIdx.y;
    const int tx = threadIdx.x, ty = threadIdx.y;
#pragma unroll
    for (int r = 0; r < 4; r++)
        tile[ty + r * 8][tx] = W[(size_t)(by * 32 + ty + r * 8) * U0 + bx * 32 + tx];
    __syncthreads();
#pragma unroll
    for (int r = 0; r < 4; r++) {
        int n = bx * 32 + ty + r * 8, k = by * 32 + tx;
        g_Wt[(size_t)n * EMBED + k] = __float2half_rn(tile[tx][ty + r * 8]);
    }
}

// ============ K3: ego columns + zero pad of g_h cols [1024,1040) ============
__global__ void ego_kernel(const float* __restrict__ ego) {
    int i = blockIdx.x * 256 + threadIdx.x;
    if (i >= BATCH * 16) return;
    int b = i >> 4, j = i & 15;
    g_h[(size_t)b * KH + U0 + j] = (j < 3) ? ego[b * 3 + j] : 0.f;
}

// ============ K4: bin rows by command (1 block, 1024 thr) ============
__global__ void prep_kernel(const int* __restrict__ cmd) {
    __shared__ int scnt[NHEAD], scur[NHEAD];
    const int tid = threadIdx.x;
    if (tid < NHEAD) scnt[tid] = 0;
    __syncthreads();
    for (int b = tid; b < BATCH; b += 1024) {
        int c = cmd[b];
        unsigned m = __match_any_sync(0xFFFFFFFFu, c);
        if ((tid & 31) == __ffs(m) - 1) atomicAdd(&scnt[c], __popc(m));
    }
    __syncthreads();
    if (tid == 0) {
        int run = 0;
        for (int g = 0; g < NHEAD; g++) { g_off[g] = run; g_cnt[g] = scnt[g]; scur[g] = run; run += scnt[g]; }
    }
    __syncthreads();
    for (int b = tid; b < BATCH; b += 1024) {
        int c = cmd[b];
        unsigned m = __match_any_sync(0xFFFFFFFFu, c);
        int leader = __ffs(m) - 1, base = 0;
        if ((tid & 31) == leader) base = atomicAdd(&scur[c], __popc(m));
        base = __shfl_sync(m, base, leader);
        g_idx[base + __popc(m & ((1u << (tid & 31)) - 1u))] = b;
    }
}

// ============ K5: GEMM1 h = relu(x @ fc_W + b), fp16 mma.sync ============
#define STG_BYTES 16384
#define NSTAGE 4
#define NITER 256

__global__ void __launch_bounds__(256, 2) gemm1_kernel(const float* __restrict__ fcb) {
    extern __shared__ char smem[];
    const uint32_t sb = smem_u32(smem);
    const int tid = threadIdx.x;
    const int wid = tid >> 5, lane = tid & 31;
    const int wm = wid & 1, wn = wid >> 1;
    const int m0 = blockIdx.y * 128, n0 = blockIdx.x * 128;

    const __half* xh = g_xh + (size_t)m0 * EMBED;
    const __half* wt = g_Wt + (size_t)n0 * EMBED;

    const int lr = tid >> 2, lc = tid & 3;
    const uint32_t lsw0 = (uint32_t)(lr * 64 + ((lc ^ ((lr >> 1) & 3)) << 4));
    const int lr1 = (tid + 256) >> 2, lc1 = (tid + 256) & 3;
    const uint32_t lsw1 = (uint32_t)(lr1 * 64 + ((lc1 ^ ((lr1 >> 1) & 3)) << 4));

#define LOAD_STAGE(stg, k0) do {                                                  \
    uint32_t bsa = sb + (stg) * STG_BYTES;                                        \
    CP_ASYNC16(bsa + lsw0, xh + (size_t)lr * EMBED + (k0) + lc * 8);              \
    CP_ASYNC16(bsa + lsw1, xh + (size_t)lr1 * EMBED + (k0) + lc1 * 8);            \
    CP_ASYNC16(bsa + 8192 + lsw0, wt + (size_t)lr * EMBED + (k0) + lc * 8);       \
    CP_ASYNC16(bsa + 8192 + lsw1, wt + (size_t)lr1 * EMBED + (k0) + lc1 * 8);     \
} while (0)

    LOAD_STAGE(0, 0);  CP_COMMIT();
    LOAD_STAGE(1, 32); CP_COMMIT();
    LOAD_STAGE(2, 64); CP_COMMIT();

    float acc[4][4][4];
#pragma unroll
    for (int f = 0; f < 4; f++)
#pragma unroll
        for (int n = 0; n < 4; n++)
#pragma unroll
            for (int j = 0; j < 4; j++) acc[f][n][j] = 0.f;

    const int trow = (lane & 7) + ((lane >> 3) & 1) * 8;
    const int tkc = lane >> 4;

    for (int it = 0; it < NITER; it++) {
        CP_WAIT2();
        __syncthreads();
        if (it + 3 < NITER) LOAD_STAGE((it + 3) & 3, (it + 3) * 32);
        CP_COMMIT();

        const uint32_t sA = sb + (it & 3) * STG_BYTES;
#pragma unroll
        for (int ks = 0; ks < 2; ks++) {
            uint32_t ah[4][4];
            uint32_t bf[4][2];
            const int kc = ks * 2 + tkc;
#pragma unroll
            for (int f = 0; f < 4; f++) {
                int row = wm * 64 + f * 16 + trow;
                uint32_t ad = sA + row * 64 + ((kc ^ ((row >> 1) & 3)) << 4);
                LDMX4(ah[f][0], ah[f][1], ah[f][2], ah[f][3], ad);
            }
#pragma unroll
            for (int p = 0; p < 2; p++) {
                int row = wn * 32 + p * 16 + trow;
                uint32_t bd = sA + 8192 + row * 64 + ((kc ^ ((row >> 1) & 3)) << 4);
                uint32_t r0, r1, r2, r3;
                LDMX4(r0, r1, r2, r3, bd);
                bf[2 * p][0] = r0; bf[2 * p][1] = r2;
                bf[2 * p + 1][0] = r1; bf[2 * p + 1][1] = r3;
            }
#pragma unroll
            for (int f = 0; f < 4; f++)
#pragma unroll
                for (int n = 0; n < 4; n++)
                    MMA16816(acc[f][n], ah[f], bf[n][0], bf[n][1]);
        }
    }

    const int qr = lane >> 2, qc = (lane & 3) << 1;
#pragma unroll
    for (int f = 0; f < 4; f++) {
#pragma unroll
        for (int n = 0; n < 4; n++) {
            int col = n0 + wn * 32 + n * 8 + qc;
            float b0 = fcb[col], b1 = fcb[col + 1];
            int row = m0 + wm * 64 + f * 16 + qr;
            float2 v0, v1;
            v0.x = fmaxf(acc[f][n][0] + b0, 0.f);
            v0.y = fmaxf(acc[f][n][1] + b1, 0.f);
            v1.x = fmaxf(acc[f][n][2] + b0, 0.f);
            v1.y = fmaxf(acc[f][n][3] + b1, 0.f);
            *reinterpret_cast<float2*>(&g_h[(size_t)row * KH + col]) = v0;
            *reinterpret_cast<float2*>(&g_h[(size_t)(row + 8) * KH + col]) = v1;
        }
    }
}

// ============ K6: binned per-head MLP, 64 rows/block, 512 threads ============
#define P2R 64
#define P2SMEM (P2R * 260 * 4)

__global__ void __launch_bounds__(512) phase2_kernel(const float* __restrict__ W1,
                                                     const float* __restrict__ b1,
                                                     const float* __restrict__ W2,
                                                     const float* __restrict__ b2,
                                                     float* __restrict__ out) {
    extern __shared__ char smem[];
    float* buf = reinterpret_cast<float*>(smem);
    __shared__ int ridx[P2R];
    const int hd = blockIdx.y;
    const int cnt = g_cnt[hd], base = g_off[hd];
    const int r0 = blockIdx.x * P2R;
    if (r0 >= cnt) return;
    const int tid = threadIdx.x;
    if (tid < P2R) {
        int rr = r0 + tid;
        ridx[tid] = g_idx[base + (rr < cnt ? rr : 0)];
    }
    __syncthreads();
    const int tx = tid & 63, ty = tid >> 6;  // 64 col-quads x 8 row-groups
    float acc[8][4];
#pragma unroll
    for (int i = 0; i < 8; i++)
#pragma unroll
        for (int j = 0; j < 4; j++) acc[i][j] = 0.f;
    const float* W1h = W1 + (size_t)hd * 1027 * 256;

    for (int kc = 0; kc < 13; kc++) {
        __syncthreads();
#pragma unroll
        for (int j = 0; j < 10; j++) {
            int q = tid + 512 * j, r = q / 80, cc = q % 80;
            buf[r * 80 + cc] = g_h[(size_t)ridx[r] * KH + kc * 80 + cc];
        }
        __syncthreads();
        const int kb = kc * 80;
#pragma unroll 8
        for (int k = 0; k < 80; k++) {
            int kk = min(kb + k, 1026);
            const float4 w = *(reinterpret_cast<const float4*>(W1h + (size_t)kk * 256) + tx);
#pragma unroll
            for (int i = 0; i < 8; i++) {
                float hv = buf[(ty * 8 + i) * 80 + k];
                acc[i][0] += hv * w.x; acc[i][1] += hv * w.y;
                acc[i][2] += hv * w.z; acc[i][3] += hv * w.w;
            }
        }
    }
    __syncthreads();
#pragma unroll
    for (int i = 0; i < 8; i++) {
        int r = ty * 8 + i;
#pragma unroll
        for (int j = 0; j < 4; j++) {
            float v = acc[i][j] + b1[hd * 256 + tx * 4 + j];
            buf[r * 260 + tx * 4 + j] = fmaxf(v, 0.f);
        }
    }
    __syncthreads();
    if (tid < 256) {
        int row = tid >> 2, o = tid & 3;  // 64 rows x 4 outputs
        const float* W2h = W2 + hd * 256 * 4;
        float a = b2[hd * 4 + o];
#pragma unroll 8
        for (int k = 0; k < 256; k++) a += buf[row * 260 + k] * W2h[k * 4 + o];
        int rr = r0 + row;
        if (rr < cnt) {
            int bi = ridx[row];
            float v;
            if (o < 2) {
                v = 5.f * tanhf(a * 0.2f);
            } else {
                float t = a + 4.9932394f;
                v = ((t > 20.f) ? t : log1pf(expf(t))) + 1e-4f;
            }
            out[bi * 4 + o] = v;
        }
    }
}

extern "C" void kernel_launch(void* const* d_in, const int* in_sizes, int n_in,
                              void* d_out, int out_size) {
    const float* x   = (const float*)d_in[0];
    const int* cmd   = (const int*)d_in[1];
    const float* ego = (const float*)d_in[2];
    const float* fcW = (const float*)d_in[3];
    const float* fcb = (const float*)d_in[4];
    const float* W1  = (const float*)d_in[5];
    const float* b1  = (const float*)d_in[6];
    const float* W2  = (const float*)d_in[7];
    const float* b2  = (const float*)d_in[8];
    float* out = (float*)d_out;

    static int smem_set = 0;
    if (!smem_set) {
        cudaFuncSetAttribute(gemm1_kernel, cudaFuncAttributeMaxDynamicSharedMemorySize,
                             NSTAGE * STG_BYTES);
        cudaFuncSetAttribute(phase2_kernel, cudaFuncAttributeMaxDynamicSharedMemorySize,
                             P2SMEM);
        smem_set = 1;
    }

    convert_x_kernel<<<(BATCH * EMBED / 4) / 256, 256>>>(x);
    convert_w_kernel<<<dim3(32, 256), dim3(32, 8)>>>(fcW);
    ego_kernel<<<(BATCH * 16) / 256, 256>>>(ego);
    prep_kernel<<<1, 1024>>>(cmd);
    gemm1_kernel<<<dim3(8, 64), 256, NSTAGE * STG_BYTES>>>(fcb);
    phase2_kernel<<<dim3(BATCH / P2R, NHEAD), 512, P2SMEM>>>(W1, b1, W2, b2, out);
}

// round 8
// speedup vs baseline: 1.5378x; 1.0008x over previous
#include <cuda_runtime.h>
#include <cuda_fp16.h>
#include <cstdint>

#define EMBED 8192
#define U0 1024
#define KH 1040
#define U1 256
#define NHEAD 6
#define BATCH 8192

__device__ __align__(16) __half g_xh[(size_t)BATCH * EMBED];
__device__ __align__(16) __half g_Wt[(size_t)U0 * EMBED];
__device__ __align__(16) float g_h[(size_t)BATCH * KH];
__device__ int g_idx[BATCH];
__device__ int g_cnt[NHEAD];
__device__ int g_off[NHEAD];

__device__ __forceinline__ uint32_t smem_u32(const void* p) {
    uint32_t a;
    asm("{ .reg .u64 t; cvta.to.shared.u64 t, %1; cvt.u32.u64 %0, t; }" : "=r"(a) : "l"(p));
    return a;
}

#define CP_ASYNC16(dst, src) \
    asm volatile("cp.async.cg.shared.global [%0], [%1], 16;" ::"r"(dst), "l"(src))
#define CP_COMMIT() asm volatile("cp.async.commit_group;" ::: "memory")
#define CP_WAIT2()  asm volatile("cp.async.wait_group 2;" ::: "memory")

#define LDMX4(r0, r1, r2, r3, a) \
    asm volatile("ldmatrix.sync.aligned.m8n8.x4.shared.b16 {%0,%1,%2,%3}, [%4];" \
        : "=r"(r0), "=r"(r1), "=r"(r2), "=r"(r3) : "r"(a))

#define MMA16816(c, a, b0, b1)                                                   \
    asm volatile("mma.sync.aligned.m16n8k16.row.col.f32.f16.f16.f32 "            \
        "{%0,%1,%2,%3}, {%4,%5,%6,%7}, {%8,%9}, {%0,%1,%2,%3};"                  \
        : "+f"((c)[0]), "+f"((c)[1]), "+f"((c)[2]), "+f"((c)[3])                 \
        : "r"((a)[0]), "r"((a)[1]), "r"((a)[2]), "r"((a)[3]), "r"(b0), "r"(b1))

// ============ K1: x -> fp16 (32B per thread) ============
__global__ void convert_x_kernel(const float* __restrict__ x) {
    size_t i = ((size_t)blockIdx.x * 512 + threadIdx.x) * 2;
    const float4 v0 = reinterpret_cast<const float4*>(x)[i];
    const float4 v1 = reinterpret_cast<const float4*>(x)[i + 1];
    uint4 ph;
    ph.x = (uint32_t)__half_as_ushort(__float2half_rn(v0.x)) |
           ((uint32_t)__half_as_ushort(__float2half_rn(v0.y)) << 16);
    ph.y = (uint32_t)__half_as_ushort(__float2half_rn(v0.z)) |
           ((uint32_t)__half_as_ushort(__float2half_rn(v0.w)) << 16);
    ph.z = (uint32_t)__half_as_ushort(__float2half_rn(v1.x)) |
           ((uint32_t)__half_as_ushort(__float2half_rn(v1.y)) << 16);
    ph.w = (uint32_t)__half_as_ushort(__float2half_rn(v1.z)) |
           ((uint32_t)__half_as_ushort(__float2half_rn(v1.w)) << 16);
    reinterpret_cast<uint4*>(g_xh)[i >> 1] = ph;
}

// ============ K2: transpose fc_W [K][N] fp32 -> g_Wt [N][K] fp16 ============
__global__ void convert_w_kernel(const float* __restrict__ W) {
    __shared__ float tile[32][33];
    const int bx = blockIdx.x, by = blockIdx.y;
    const int tx = threadIdx.x, ty = threadIdx.y;
#pragma unroll
    for (int r = 0; r < 4; r++)
        tile[ty + r * 8][tx] = W[(size_t)(by * 32 + ty + r * 8) * U0 + bx * 32 + tx];
    __syncthreads();
#pragma unroll
    for (int r = 0; r < 4; r++) {
        int n = bx * 32 + ty + r * 8, k = by * 32 + tx;
        g_Wt[(size_t)n * EMBED + k] = __float2half_rn(tile[tx][ty + r * 8]);
    }
}

// ============ K3: ego columns + zero pad of g_h cols [1024,1040) ============
__global__ void ego_kernel(const float* __restrict__ ego) {
    int i = blockIdx.x * 256 + threadIdx.x;
    if (i >= BATCH * 16) return;
    int b = i >> 4, j = i & 15;
    g_h[(size_t)b * KH + U0 + j] = (j < 3) ? ego[b * 3 + j] : 0.f;
}

// ============ K4: bin rows by command (1 block, 1024 thr) ============
__global__ void prep_kernel(const int* __restrict__ cmd) {
    __shared__ int scnt[NHEAD], scur[NHEAD];
    const int tid = threadIdx.x;
    if (tid < NHEAD) scnt[tid] = 0;
    __syncthreads();
    for (int b = tid; b < BATCH; b += 1024) {
        int c = cmd[b];
        unsigned m = __match_any_sync(0xFFFFFFFFu, c);
        if ((tid & 31) == __ffs(m) - 1) atomicAdd(&scnt[c], __popc(m));
    }
    __syncthreads();
    if (tid == 0) {
        int run = 0;
        for (int g = 0; g < NHEAD; g++) { g_off[g] = run; g_cnt[g] = scnt[g]; scur[g] = run; run += scnt[g]; }
    }
    __syncthreads();
    for (int b = tid; b < BATCH; b += 1024) {
        int c = cmd[b];
        unsigned m = __match_any_sync(0xFFFFFFFFu, c);
        int leader = __ffs(m) - 1, base = 0;
        if ((tid & 31) == leader) base = atomicAdd(&scur[c], __popc(m));
        base = __shfl_sync(m, base, leader);
        g_idx[base + __popc(m & ((1u << (tid & 31)) - 1u))] = b;
    }
}

// ============ K5: GEMM1 h = relu(x @ fc_W + b), fp16 mma.sync ============
// BM=128 BN=128 BK=32, 512 threads (16 warps as 4m x 4n, m32 x n32 per warp),
// 4-stage cp.async. Stage (16 KB): A [128][32]h @+0, W [128][32]h @+8192.
#define STG_BYTES 16384
#define NSTAGE 4
#define NITER 256

__global__ void __launch_bounds__(512) gemm1_kernel(const float* __restrict__ fcb) {
    extern __shared__ char smem[];
    const uint32_t sb = smem_u32(smem);
    const int tid = threadIdx.x;
    const int wid = tid >> 5, lane = tid & 31;
    const int wm = wid & 3, wn = wid >> 2;
    const int m0 = blockIdx.y * 128, n0 = blockIdx.x * 128;

    const __half* xh = g_xh + (size_t)m0 * EMBED;
    const __half* wt = g_Wt + (size_t)n0 * EMBED;

    // 512 threads cover one 128x32 fp16 tile (16B chunks) exactly
    const int lr = tid >> 2, lc = tid & 3;
    const uint32_t lsw0 = (uint32_t)(lr * 64 + ((lc ^ ((lr >> 1) & 3)) << 4));

#define LOAD_STAGE(stg, k0) do {                                                  \
    uint32_t bsa = sb + (stg) * STG_BYTES;                                        \
    CP_ASYNC16(bsa + lsw0, xh + (size_t)lr * EMBED + (k0) + lc * 8);              \
    CP_ASYNC16(bsa + 8192 + lsw0, wt + (size_t)lr * EMBED + (k0) + lc * 8);       \
} while (0)

    LOAD_STAGE(0, 0);  CP_COMMIT();
    LOAD_STAGE(1, 32); CP_COMMIT();
    LOAD_STAGE(2, 64); CP_COMMIT();

    float acc[2][4][4];
#pragma unroll
    for (int f = 0; f < 2; f++)
#pragma unroll
        for (int n = 0; n < 4; n++)
#pragma unroll
            for (int j = 0; j < 4; j++) acc[f][n][j] = 0.f;

    const int trow = (lane & 7) + ((lane >> 3) & 1) * 8;
    const int tkc = lane >> 4;

    for (int it = 0; it < NITER; it++) {
        CP_WAIT2();
        __syncthreads();
        if (it + 3 < NITER) LOAD_STAGE((it + 3) & 3, (it + 3) * 32);
        CP_COMMIT();

        const uint32_t sA = sb + (it & 3) * STG_BYTES;
#pragma unroll
        for (int ks = 0; ks < 2; ks++) {
            uint32_t ah[2][4];
            uint32_t bf[4][2];
            const int kc = ks * 2 + tkc;
#pragma unroll
            for (int f = 0; f < 2; f++) {
                int row = wm * 32 + f * 16 + trow;
                uint32_t ad = sA + row * 64 + ((kc ^ ((row >> 1) & 3)) << 4);
                LDMX4(ah[f][0], ah[f][1], ah[f][2], ah[f][3], ad);
            }
#pragma unroll
            for (int p = 0; p < 2; p++) {
                int row = wn * 32 + p * 16 + trow;
                uint32_t bd = sA + 8192 + row * 64 + ((kc ^ ((row >> 1) & 3)) << 4);
                uint32_t r0, r1, r2, r3;
                LDMX4(r0, r1, r2, r3, bd);
                bf[2 * p][0] = r0; bf[2 * p][1] = r2;
                bf[2 * p + 1][0] = r1; bf[2 * p + 1][1] = r3;
            }
#pragma unroll
            for (int f = 0; f < 2; f++)
#pragma unroll
                for (int n = 0; n < 4; n++)
                    MMA16816(acc[f][n], ah[f], bf[n][0], bf[n][1]);
        }
    }

    const int qr = lane >> 2, qc = (lane & 3) << 1;
#pragma unroll
    for (int f = 0; f < 2; f++) {
#pragma unroll
        for (int n = 0; n < 4; n++) {
            int col = n0 + wn * 32 + n * 8 + qc;
            float b0 = fcb[col], b1 = fcb[col + 1];
            int row = m0 + wm * 32 + f * 16 + qr;
            float2 v0, v1;
            v0.x = fmaxf(acc[f][n][0] + b0, 0.f);
            v0.y = fmaxf(acc[f][n][1] + b1, 0.f);
            v1.x = fmaxf(acc[f][n][2] + b0, 0.f);
            v1.y = fmaxf(acc[f][n][3] + b1, 0.f);
            *reinterpret_cast<float2*>(&g_h[(size_t)row * KH + col]) = v0;
            *reinterpret_cast<float2*>(&g_h[(size_t)(row + 8) * KH + col]) = v1;
        }
    }
}

// ============ K6: binned per-head MLP, 64 rows/block, 512 threads ============
#define P2R 64
#define P2SMEM (P2R * 260 * 4)

__global__ void __launch_bounds__(512) phase2_kernel(const float* __restrict__ W1,
                                                     const float* __restrict__ b1,
                                                     const float* __restrict__ W2,
                                                     const float* __restrict__ b2,
                                                     float* __restrict__ out) {
    extern __shared__ char smem[];
    float* buf = reinterpret_cast<float*>(smem);
    __shared__ int ridx[P2R];
    const int hd = blockIdx.y;
    const int cnt = g_cnt[hd], base = g_off[hd];
    const int r0 = blockIdx.x * P2R;
    if (r0 >= cnt) return;
    const int tid = threadIdx.x;
    if (tid < P2R) {
        int rr = r0 + tid;
        ridx[tid] = g_idx[base + (rr < cnt ? rr : 0)];
    }
    __syncthreads();
    const int tx = tid & 63, ty = tid >> 6;  // 64 col-quads x 8 row-groups
    float acc[8][4];
#pragma unroll
    for (int i = 0; i < 8; i++)
#pragma unroll
        for (int j = 0; j < 4; j++) acc[i][j] = 0.f;
    const float* W1h = W1 + (size_t)hd * 1027 * 256;

    for (int kc = 0; kc < 13; kc++) {
        __syncthreads();
#pragma unroll
        for (int j = 0; j < 10; j++) {
            int q = tid + 512 * j, r = q / 80, cc = q % 80;
            buf[r * 80 + cc] = g_h[(size_t)ridx[r] * KH + kc * 80 + cc];
        }
        __syncthreads();
        const int kb = kc * 80;
#pragma unroll 8
        for (int k = 0; k < 80; k++) {
            int kk = min(kb + k, 1026);
            const float4 w = *(reinterpret_cast<const float4*>(W1h + (size_t)kk * 256) + tx);
#pragma unroll
            for (int i = 0; i < 8; i++) {
                float hv = buf[(ty * 8 + i) * 80 + k];
                acc[i][0] += hv * w.x; acc[i][1] += hv * w.y;
                acc[i][2] += hv * w.z; acc[i][3] += hv * w.w;
            }
        }
    }
    __syncthreads();
#pragma unroll
    for (int i = 0; i < 8; i++) {
        int r = ty * 8 + i;
#pragma unroll
        for (int j = 0; j < 4; j++) {
            float v = acc[i][j] + b1[hd * 256 + tx * 4 + j];
            buf[r * 260 + tx * 4 + j] = fmaxf(v, 0.f);
        }
    }
    __syncthreads();
    if (tid < 256) {
        int row = tid >> 2, o = tid & 3;  // 64 rows x 4 outputs
        const float* W2h = W2 + hd * 256 * 4;
        float a = b2[hd * 4 + o];
#pragma unroll 8
        for (int k = 0; k < 256; k++) a += buf[row * 260 + k] * W2h[k * 4 + o];
        int rr = r0 + row;
        if (rr < cnt) {
            int bi = ridx[row];
            float v;
            if (o < 2) {
                v = 5.f * tanhf(a * 0.2f);
            } else {
                float t = a + 4.9932394f;
                v = ((t > 20.f) ? t : log1pf(expf(t))) + 1e-4f;
            }
            out[bi * 4 + o] = v;
        }
    }
}

extern "C" void kernel_launch(void* const* d_in, const int* in_sizes, int n_in,
                              void* d_out, int out_size) {
    const float* x   = (const float*)d_in[0];
    const int* cmd   = (const int*)d_in[1];
    const float* ego = (const float*)d_in[2];
    const float* fcW = (const float*)d_in[3];
    const float* fcb = (const float*)d_in[4];
    const float* W1  = (const float*)d_in[5];
    const float* b1  = (const float*)d_in[6];
    const float* W2  = (const float*)d_in[7];
    const float* b2  = (const float*)d_in[8];
    float* out = (float*)d_out;

    static int smem_set = 0;
    if (!smem_set) {
        cudaFuncSetAttribute(gemm1_kernel, cudaFuncAttributeMaxDynamicSharedMemorySize,
                             NSTAGE * STG_BYTES);
        cudaFuncSetAttribute(phase2_kernel, cudaFuncAttributeMaxDynamicSharedMemorySize,
                             P2SMEM);
        smem_set = 1;
    }

    convert_x_kernel<<<(BATCH * EMBED / 8) / 512, 512>>>(x);
    convert_w_kernel<<<dim3(32, 256), dim3(32, 8)>>>(fcW);
    ego_kernel<<<(BATCH * 16) / 256, 256>>>(ego);
    prep_kernel<<<1, 1024>>>(cmd);
    gemm1_kernel<<<dim3(8, 64), 512, NSTAGE * STG_BYTES>>>(fcb);
    phase2_kernel<<<dim3(BATCH / P2R, NHEAD), 512, P2SMEM>>>(W1, b1, W2, b2, out);
}

// round 12
// speedup vs baseline: 2.2359x; 1.4540x over previous
#include <cuda_runtime.h>
#include <cuda_fp16.h>
#include <cstdint>

#define EMBED 8192
#define U0 1024
#define KH 1040
#define U1 256
#define NHEAD 6
#define BATCH 8192

__device__ __align__(16) __half g_xh[(size_t)BATCH * EMBED];
__device__ __align__(16) __half g_Wt[(size_t)U0 * EMBED];
__device__ __align__(16) __half g_hh[(size_t)BATCH * KH];
__device__ __align__(16) __half g_W1t[(size_t)NHEAD * U1 * KH];
__device__ int g_idx[BATCH];
__device__ int g_cnt[NHEAD];
__device__ int g_off[NHEAD];

__device__ __forceinline__ uint32_t smem_u32(const void* p) {
    uint32_t a;
    asm("{ .reg .u64 t; cvta.to.shared.u64 t, %1; cvt.u32.u64 %0, t; }" : "=r"(a) : "l"(p));
    return a;
}

#define CP_ASYNC16(dst, src) \
    asm volatile("cp.async.cg.shared.global [%0], [%1], 16;" ::"r"(dst), "l"(src))
#define CP_COMMIT() asm volatile("cp.async.commit_group;" ::: "memory")
#define CP_WAIT2()  asm volatile("cp.async.wait_group 2;" ::: "memory")
#define CP_WAIT1()  asm volatile("cp.async.wait_group 1;" ::: "memory")

#define LDMX4(r0, r1, r2, r3, a) \
    asm volatile("ldmatrix.sync.aligned.m8n8.x4.shared.b16 {%0,%1,%2,%3}, [%4];" \
        : "=r"(r0), "=r"(r1), "=r"(r2), "=r"(r3) : "r"(a))

#define MMA16816(c, a, b0, b1)                                                   \
    asm volatile("mma.sync.aligned.m16n8k16.row.col.f32.f16.f16.f32 "            \
        "{%0,%1,%2,%3}, {%4,%5,%6,%7}, {%8,%9}, {%0,%1,%2,%3};"                  \
        : "+f"((c)[0]), "+f"((c)[1]), "+f"((c)[2]), "+f"((c)[3])                 \
        : "r"((a)[0]), "r"((a)[1]), "r"((a)[2]), "r"((a)[3]), "r"(b0), "r"(b1))

// ============ K1: x -> fp16 (32B per thread) ============
__global__ void convert_x_kernel(const float* __restrict__ x) {
    size_t i = ((size_t)blockIdx.x * 512 + threadIdx.x) * 2;
    const float4 v0 = reinterpret_cast<const float4*>(x)[i];
    const float4 v1 = reinterpret_cast<const float4*>(x)[i + 1];
    uint4 ph;
    ph.x = (uint32_t)__half_as_ushort(__float2half_rn(v0.x)) |
           ((uint32_t)__half_as_ushort(__float2half_rn(v0.y)) << 16);
    ph.y = (uint32_t)__half_as_ushort(__float2half_rn(v0.z)) |
           ((uint32_t)__half_as_ushort(__float2half_rn(v0.w)) << 16);
    ph.z = (uint32_t)__half_as_ushort(__float2half_rn(v1.x)) |
           ((uint32_t)__half_as_ushort(__float2half_rn(v1.y)) << 16);
    ph.w = (uint32_t)__half_as_ushort(__float2half_rn(v1.z)) |
           ((uint32_t)__half_as_ushort(__float2half_rn(v1.w)) << 16);
    reinterpret_cast<uint4*>(g_xh)[i >> 1] = ph;
}

// ============ K2: transpose fc_W [K][N] fp32 -> g_Wt [N][K] fp16 ============
__global__ void convert_w_kernel(const float* __restrict__ W) {
    __shared__ float tile[32][33];
    const int bx = blockIdx.x, by = blockIdx.y;
    const int tx = threadIdx.x, ty = threadIdx.y;
#pragma unroll
    for (int r = 0; r < 4; r++)
        tile[ty + r * 8][tx] = W[(size_t)(by * 32 + ty + r * 8) * U0 + bx * 32 + tx];
    __syncthreads();
#pragma unroll
    for (int r = 0; r < 4; r++) {
        int n = bx * 32 + ty + r * 8, k = by * 32 + tx;
        g_Wt[(size_t)n * EMBED + k] = __float2half_rn(tile[tx][ty + r * 8]);
    }
}

// ============ K2b: W1 [h][k(1027)][n(256)] -> g_W1t [h][n][k(1040 pad)] fp16 ============
__global__ void convert_w1_kernel(const float* __restrict__ W1) {
    __shared__ float tile[32][33];
    const int kt = blockIdx.x, nt = blockIdx.y, hd = blockIdx.z;
    const int tx = threadIdx.x, ty = threadIdx.y;
    const float* Wh = W1 + (size_t)hd * 1027 * 256;
#pragma unroll
    for (int r = 0; r < 4; r++) {
        int k = kt * 32 + ty + r * 8, n = nt * 32 + tx;
        tile[ty + r * 8][tx] = (k < 1027) ? Wh[(size_t)k * 256 + n] : 0.f;
    }
    __syncthreads();
#pragma unroll
    for (int r = 0; r < 4; r++) {
        int n = nt * 32 + ty + r * 8, k = kt * 32 + tx;
        if (k < KH)
            g_W1t[(size_t)hd * U1 * KH + (size_t)n * KH + k] = __float2half_rn(tile[tx][ty + r * 8]);
    }
}

// ============ K3: ego columns + zero pad of g_hh cols [1024,1040) fp16 ============
__global__ void ego_kernel(const float* __restrict__ ego) {
    int i = blockIdx.x * 256 + threadIdx.x;
    if (i >= BATCH * 16) return;
    int b = i >> 4, j = i & 15;
    g_hh[(size_t)b * KH + U0 + j] = __float2half_rn((j < 3) ? ego[b * 3 + j] : 0.f);
}

// ============ K4: bin rows by command (1 block, 1024 thr) ============
__global__ void prep_kernel(const int* __restrict__ cmd) {
    __shared__ int scnt[NHEAD], scur[NHEAD];
    const int tid = threadIdx.x;
    if (tid < NHEAD) scnt[tid] = 0;
    __syncthreads();
    for (int b = tid; b < BATCH; b += 1024) {
        int c = cmd[b];
        unsigned m = __match_any_sync(0xFFFFFFFFu, c);
        if ((tid & 31) == __ffs(m) - 1) atomicAdd(&scnt[c], __popc(m));
    }
    __syncthreads();
    if (tid == 0) {
        int run = 0;
        for (int g = 0; g < NHEAD; g++) { g_off[g] = run; g_cnt[g] = scnt[g]; scur[g] = run; run += scnt[g]; }
    }
    __syncthreads();
    for (int b = tid; b < BATCH; b += 1024) {
        int c = cmd[b];
        unsigned m = __match_any_sync(0xFFFFFFFFu, c);
        int leader = __ffs(m) - 1, base = 0;
        if ((tid & 31) == leader) base = atomicAdd(&scur[c], __popc(m));
        base = __shfl_sync(m, base, leader);
        g_idx[base + __popc(m & ((1u << (tid & 31)) - 1u))] = b;
    }
}

// ============ K5: GEMM1 h = relu(x @ fc_W + b) -> g_hh fp16, mma.sync ============
#define STG_BYTES 16384
#define NSTAGE 4
#define NITER 256

__global__ void __launch_bounds__(512) gemm1_kernel(const float* __restrict__ fcb) {
    extern __shared__ char smem[];
    const uint32_t sb = smem_u32(smem);
    const int tid = threadIdx.x;
    const int wid = tid >> 5, lane = tid & 31;
    const int wm = wid & 3, wn = wid >> 2;
    const int m0 = blockIdx.y * 128, n0 = blockIdx.x * 128;

    const __half* xh = g_xh + (size_t)m0 * EMBED;
    const __half* wt = g_Wt + (size_t)n0 * EMBED;

    const int lr = tid >> 2, lc = tid & 3;
    const uint32_t lsw0 = (uint32_t)(lr * 64 + ((lc ^ ((lr >> 1) & 3)) << 4));

#define LOAD_STAGE(stg, k0) do {                                                  \
    uint32_t bsa = sb + (stg) * STG_BYTES;                                        \
    CP_ASYNC16(bsa + lsw0, xh + (size_t)lr * EMBED + (k0) + lc * 8);              \
    CP_ASYNC16(bsa + 8192 + lsw0, wt + (size_t)lr * EMBED + (k0) + lc * 8);       \
} while (0)

    LOAD_STAGE(0, 0);  CP_COMMIT();
    LOAD_STAGE(1, 32); CP_COMMIT();
    LOAD_STAGE(2, 64); CP_COMMIT();

    float acc[2][4][4];
#pragma unroll
    for (int f = 0; f < 2; f++)
#pragma unroll
        for (int n = 0; n < 4; n++)
#pragma unroll
            for (int j = 0; j < 4; j++) acc[f][n][j] = 0.f;

    const int trow = (lane & 7) + ((lane >> 3) & 1) * 8;
    const int tkc = lane >> 4;

    for (int it = 0; it < NITER; it++) {
        CP_WAIT2();
        __syncthreads();
        if (it + 3 < NITER) LOAD_STAGE((it + 3) & 3, (it + 3) * 32);
        CP_COMMIT();

        const uint32_t sA = sb + (it & 3) * STG_BYTES;
#pragma unroll
        for (int ks = 0; ks < 2; ks++) {
            uint32_t ah[2][4];
            uint32_t bf[4][2];
            const int kc = ks * 2 + tkc;
#pragma unroll
            for (int f = 0; f < 2; f++) {
                int row = wm * 32 + f * 16 + trow;
                uint32_t ad = sA + row * 64 + ((kc ^ ((row >> 1) & 3)) << 4);
                LDMX4(ah[f][0], ah[f][1], ah[f][2], ah[f][3], ad);
            }
#pragma unroll
            for (int p = 0; p < 2; p++) {
                int row = wn * 32 + p * 16 + trow;
                uint32_t bd = sA + 8192 + row * 64 + ((kc ^ ((row >> 1) & 3)) << 4);
                uint32_t r0, r1, r2, r3;
                LDMX4(r0, r1, r2, r3, bd);
                bf[2 * p][0] = r0; bf[2 * p][1] = r2;
                bf[2 * p + 1][0] = r1; bf[2 * p + 1][1] = r3;
            }
#pragma unroll
            for (int f = 0; f < 2; f++)
#pragma unroll
                for (int n = 0; n < 4; n++)
                    MMA16816(acc[f][n], ah[f], bf[n][0], bf[n][1]);
        }
    }

    const int qr = lane >> 2, qc = (lane & 3) << 1;
#pragma unroll
    for (int f = 0; f < 2; f++) {
#pragma unroll
        for (int n = 0; n < 4; n++) {
            int col = n0 + wn * 32 + n * 8 + qc;
            float b0 = fcb[col], b1 = fcb[col + 1];
            int row = m0 + wm * 32 + f * 16 + qr;
            __half2 v0, v1;
            v0.x = __float2half_rn(fmaxf(acc[f][n][0] + b0, 0.f));
            v0.y = __float2half_rn(fmaxf(acc[f][n][1] + b1, 0.f));
            v1.x = __float2half_rn(fmaxf(acc[f][n][2] + b0, 0.f));
            v1.y = __float2half_rn(fmaxf(acc[f][n][3] + b1, 0.f));
            *reinterpret_cast<__half2*>(&g_hh[(size_t)row * KH + col]) = v0;
            *reinterpret_cast<__half2*>(&g_hh[(size_t)(row + 8) * KH + col]) = v1;
        }
    }
}

// ============ K6: phase2 via tensor cores ============
// Per block: 64 gathered rows x 256 cols, K=1040 in 13 chunks of 80.
// smem stage: A 64x176B + B 256x176B = 56320 B, double buffered.
// 256 threads, 8 warps as 2m x 4n (warp m32 x n64).
#define P2_STG 56320
#define P2_BOFF 11264
#define P2SMEM (2 * P2_STG)

__global__ void __launch_bounds__(256) phase2_kernel(const float* __restrict__ b1,
                                                     const float* __restrict__ W2,
                                                     const float* __restrict__ b2,
                                                     float* __restrict__ out) {
    extern __shared__ char smem[];
    const uint32_t sb = smem_u32(smem);
    __shared__ int ridx[64];
    const int hd = blockIdx.y;
    const int cnt = g_cnt[hd], base = g_off[hd];
    const int r0 = blockIdx.x * 64;
    if (r0 >= cnt) return;
    const int tid = threadIdx.x;
    const int wid = tid >> 5, lane = tid & 31;
    const int wm = wid & 1, wn = wid >> 1;
    if (tid < 64) {
        int rr = r0 + tid;
        ridx[tid] = g_idx[base + (rr < cnt ? rr : 0)];
    }
    __syncthreads();

    const __half* W1h = g_W1t + (size_t)hd * U1 * KH;

// NOTE: all internal identifiers are suffixed to avoid capturing the caller's
// loop variable in the kb/stg argument expressions (R9 bug: inner `c` shadowed
// the outer chunk index inside `(kb)`).
#define P2_LOAD(stg, kb) do {                                                     \
    const int kb_ = (kb);                                                         \
    const uint32_t sa_ = sb + (stg) * P2_STG;                                     \
    _Pragma("unroll")                                                             \
    for (int j_ = 0; j_ < 3; j_++) {                                              \
        int q_ = tid + 256 * j_;                                                  \
        if (q_ < 640) {                                                           \
            int r_ = q_ / 10, c_ = q_ % 10;                                       \
            CP_ASYNC16(sa_ + r_ * 176 + c_ * 16,                                  \
                       g_hh + (size_t)ridx[r_] * KH + kb_ + c_ * 8);              \
        }                                                                         \
    }                                                                             \
    _Pragma("unroll")                                                             \
    for (int j_ = 0; j_ < 10; j_++) {                                             \
        int q_ = tid + 256 * j_;                                                  \
        int r_ = q_ / 10, c_ = q_ % 10;                                           \
        CP_ASYNC16(sa_ + P2_BOFF + r_ * 176 + c_ * 16,                            \
                   W1h + (size_t)r_ * KH + kb_ + c_ * 8);                         \
    }                                                                             \
} while (0)

    float acc[2][8][4];
#pragma unroll
    for (int f = 0; f < 2; f++)
#pragma unroll
        for (int n = 0; n < 8; n++)
#pragma unroll
            for (int j = 0; j < 4; j++) acc[f][n][j] = 0.f;

    const int trow = (lane & 7) + ((lane >> 3) & 1) * 8;
    const int tkc = lane >> 4;

    P2_LOAD(0, 0);
    CP_COMMIT();

    for (int c = 0; c < 13; c++) {
        if (c + 1 < 13) P2_LOAD((c + 1) & 1, (c + 1) * 80);
        CP_COMMIT();
        CP_WAIT1();
        __syncthreads();
        const uint32_t sa = sb + (c & 1) * P2_STG;
#pragma unroll
        for (int kk = 0; kk < 5; kk++) {
            const int kc = kk * 2 + tkc;
            uint32_t ah[2][4];
            uint32_t bf[8][2];
#pragma unroll
            for (int f = 0; f < 2; f++) {
                int row = wm * 32 + f * 16 + trow;
                LDMX4(ah[f][0], ah[f][1], ah[f][2], ah[f][3], sa + row * 176 + kc * 16);
            }
#pragma unroll
            for (int p = 0; p < 4; p++) {
                int row = wn * 64 + p * 16 + trow;
                uint32_t r0_, r1_, r2_, r3_;
                LDMX4(r0_, r1_, r2_, r3_, sa + P2_BOFF + row * 176 + kc * 16);
                bf[2 * p][0] = r0_; bf[2 * p][1] = r2_;
                bf[2 * p + 1][0] = r1_; bf[2 * p + 1][1] = r3_;
            }
#pragma unroll
            for (int f = 0; f < 2; f++)
#pragma unroll
                for (int n = 0; n < 8; n++)
                    MMA16816(acc[f][n], ah[f], bf[n][0], bf[n][1]);
        }
        __syncthreads();
    }

    // h1 = relu(acc + b1) -> smem fp32 [64][264]
    float* buf = reinterpret_cast<float*>(smem);
    const int qr = lane >> 2, qc = (lane & 3) << 1;
    __syncthreads();
#pragma unroll
    for (int f = 0; f < 2; f++) {
#pragma unroll
        for (int n = 0; n < 8; n++) {
            int col = wn * 64 + n * 8 + qc;
            float bb0 = b1[hd * 256 + col], bb1 = b1[hd * 256 + col + 1];
            int row = wm * 32 + f * 16 + qr;
            buf[row * 264 + col] = fmaxf(acc[f][n][0] + bb0, 0.f);
            buf[row * 264 + col + 1] = fmaxf(acc[f][n][1] + bb1, 0.f);
            buf[(row + 8) * 264 + col] = fmaxf(acc[f][n][2] + bb0, 0.f);
            buf[(row + 8) * 264 + col + 1] = fmaxf(acc[f][n][3] + bb1, 0.f);
        }
    }
    __syncthreads();

    // h2 = h1 @ W2 + b2, epilogue
    {
        int row = tid >> 2, o = tid & 3;
        const float* W2h = W2 + hd * 256 * 4;
        float a = b2[hd * 4 + o];
#pragma unroll 8
        for (int k = 0; k < 256; k++) a += buf[row * 264 + k] * W2h[k * 4 + o];
        int rr = r0 + row;
        if (rr < cnt) {
            int bi = ridx[row];
            float v;
            if (o < 2) {
                v = 5.f * tanhf(a * 0.2f);
            } else {
                float t = a + 4.9932394f;
                v = ((t > 20.f) ? t : log1pf(expf(t))) + 1e-4f;
            }
            out[bi * 4 + o] = v;
        }
    }
}

extern "C" void kernel_launch(void* const* d_in, const int* in_sizes, int n_in,
                              void* d_out, int out_size) {
    const float* x   = (const float*)d_in[0];
    const int* cmd   = (const int*)d_in[1];
    const float* ego = (const float*)d_in[2];
    const float* fcW = (const float*)d_in[3];
    const float* fcb = (const float*)d_in[4];
    const float* W1  = (const float*)d_in[5];
    const float* b1  = (const float*)d_in[6];
    const float* W2  = (const float*)d_in[7];
    const float* b2  = (const float*)d_in[8];
    float* out = (float*)d_out;

    static int smem_set = 0;
    if (!smem_set) {
        cudaFuncSetAttribute(gemm1_kernel, cudaFuncAttributeMaxDynamicSharedMemorySize,
                             NSTAGE * STG_BYTES);
        cudaFuncSetAttribute(phase2_kernel, cudaFuncAttributeMaxDynamicSharedMemorySize,
                             P2SMEM);
        smem_set = 1;
    }

    convert_x_kernel<<<(BATCH * EMBED / 8) / 512, 512>>>(x);
    convert_w_kernel<<<dim3(32, 256), dim3(32, 8)>>>(fcW);
    convert_w1_kernel<<<dim3(33, 8, NHEAD), dim3(32, 8)>>>(W1);
    ego_kernel<<<(BATCH * 16) / 256, 256>>>(ego);
    prep_kernel<<<1, 1024>>>(cmd);
    gemm1_kernel<<<dim3(8, 64), 512, NSTAGE * STG_BYTES>>>(fcb);
    phase2_kernel<<<dim3(BATCH / 64, NHEAD), 256, P2SMEM>>>(b1, W2, b2, out);
}